// round 11
// baseline (speedup 1.0000x reference)
#include <cuda_runtime.h>
#include <cuda_fp16.h>
#include <cstdint>

// Problem constants
#define BB  32
#define TT  256
#define DD  512
#define MPP 20

constexpr int TM     = 128;            // CTA t rows
constexpr int TN     = 32;             // s cols per verified chunk
constexpr int NCHK   = TT / TN;        // 8 s-chunks
constexpr int NM     = 5;              // m-planes per CTA (20 = 4 groups of 5)
constexpr int KC     = 64;             // k per pipeline stage (4 x k16)
constexpr int NST    = DD / KC;        // 8 stages
constexpr int STAGES = 4;              // buffer ring depth
constexpr int ROWB   = 144;            // smem row bytes: 128B data + 16B pad
constexpr int A_BYTES   = TM * ROWB;              // 18432
constexpr int B_BYTES   = TN * ROWB;              // 4608
constexpr int STG_BYTES = A_BYTES + B_BYTES;      // 23040

constexpr int S_KMS  = 0;              // 5*512 halves = 5120 B
constexpr int S_MBAR = 5120;           // 8 x 8B mbarriers (4 full + 4 empty)
constexpr int S_BUF  = 5248;           // 128B aligned
constexpr int S_TOTAL = S_BUF + STAGES * STG_BYTES;  // 97408 B

constexpr float THRESH = 10.0f;        // tanh(10) = 1 - 4.1e-9; monotone-safe exit

// static device scratch (allocation-free per harness rules)
__device__ __half g_lt[BB * TT * DD];
__device__ __half g_rt[BB * TT * DD];

static __device__ __forceinline__ uint32_t s2u(const void* p) {
    return (uint32_t)__cvta_generic_to_shared(p);
}

#define CP16(dst, src) \
    asm volatile("cp.async.cg.shared.global [%0], [%1], 16;" :: "r"(dst), "l"(src))

#define LDSM4(r0, r1, r2, r3, addr)                                              \
    asm volatile("ldmatrix.sync.aligned.m8n8.x4.shared.b16 {%0,%1,%2,%3}, [%4];" \
                 : "=r"(r0), "=r"(r1), "=r"(r2), "=r"(r3) : "r"(addr))

#define MMA16816(d0, d1, a0, a1, a2, a3, b0, b1)                                  \
    asm volatile("mma.sync.aligned.m16n8k16.row.col.f16.f16.f16.f16 "             \
                 "{%0,%1},{%2,%3,%4,%5},{%6,%7},{%0,%1};"                         \
                 : "+r"(d0), "+r"(d1)                                             \
                 : "r"(a0), "r"(a1), "r"(a2), "r"(a3), "r"(b0), "r"(b1))

// spin (with suspend hint) until the mbarrier phase with given parity completes
#define MBWAIT(addr, ph)                                                          \
    asm volatile("{\n\t.reg .pred P;\n\t"                                         \
                 "MBW%=:\n\t"                                                     \
                 "mbarrier.try_wait.parity.shared.b64 P, [%0], %1, 0x989680;\n\t" \
                 "@!P bra MBW%=;\n\t}"                                            \
                 :: "r"(addr), "r"(ph) : "memory")

static __device__ __forceinline__ uint32_t hmul2u(uint32_t a, uint32_t b) {
    __half2 r = __hmul2(*reinterpret_cast<__half2*>(&a),
                        *reinterpret_cast<__half2*>(&b));
    return *reinterpret_cast<uint32_t*>(&r);
}

// ---------------------------------------------------------------------------
// Kernel 1: fp32 -> fp16 conversion of lt and rt (16 floats/tensor/thread)
// ---------------------------------------------------------------------------
__global__ void cvt_kernel(const float* __restrict__ lt, const float* __restrict__ rt) {
    int i = blockIdx.x * blockDim.x + threadIdx.x;  // 16-float unit index
    const float4* pl = reinterpret_cast<const float4*>(lt) + i * 4;
    const float4* pr = reinterpret_cast<const float4*>(rt) + i * 4;
    float4 a[4], b[4];
#pragma unroll
    for (int j = 0; j < 4; j++) a[j] = pl[j];
#pragma unroll
    for (int j = 0; j < 4; j++) b[j] = pr[j];

    uint32_t wa[8], wb[8];
#pragma unroll
    for (int j = 0; j < 4; j++) {
        __half2 h0 = __floats2half2_rn(a[j].x, a[j].y);
        __half2 h1 = __floats2half2_rn(a[j].z, a[j].w);
        wa[j * 2]     = *reinterpret_cast<uint32_t*>(&h0);
        wa[j * 2 + 1] = *reinterpret_cast<uint32_t*>(&h1);
        __half2 g0 = __floats2half2_rn(b[j].x, b[j].y);
        __half2 g1 = __floats2half2_rn(b[j].z, b[j].w);
        wb[j * 2]     = *reinterpret_cast<uint32_t*>(&g0);
        wb[j * 2 + 1] = *reinterpret_cast<uint32_t*>(&g1);
    }
    uint4* dl = reinterpret_cast<uint4*>(g_lt + (size_t)i * 16);
    uint4* dr = reinterpret_cast<uint4*>(g_rt + (size_t)i * 16);
    dl[0] = make_uint4(wa[0], wa[1], wa[2], wa[3]);
    dl[1] = make_uint4(wa[4], wa[5], wa[6], wa[7]);
    dr[0] = make_uint4(wb[0], wb[1], wb[2], wb[3]);
    dr[1] = make_uint4(wb[4], wb[5], wb[6], wb[7]);
}

// ---------------------------------------------------------------------------
// Kernel 2: one CTA = (b, t-tile 128, 5 m-planes). s in chunks of 32 with
// monotone-safe early exit (exact fallback over all 8 chunks). 8 warps,
// warp tile 16t x 32s x 5m, fp16 HMMA fp16-acc, km folded in registers.
// mbarrier-decoupled cp.async pipeline (full: 256 cp.async .noinc arrivals;
// empty: 8 warp arrivals) — per-warp progression, no CTA-wide barrier in the
// steady state. Grid = 256 CTAs <= 296 slots.
// ---------------------------------------------------------------------------
__global__ __launch_bounds__(256, 2)
void match_kernel(const float* __restrict__ kw, float* __restrict__ out) {
    extern __shared__ __align__(128) char smem[];
    const int tid = threadIdx.x;
    const int b   = blockIdx.z;
    const int m0  = blockIdx.y * NM;
    const int t0  = blockIdx.x * TM;
    const uint32_t sbase   = s2u(smem);
    const uint32_t sbuf    = sbase + S_BUF;
    const uint32_t mbfull  = sbase + S_MBAR;        // 4 x 8B
    const uint32_t mbempty = sbase + S_MBAR + 32;   // 4 x 8B

    if (tid == 0) {
#pragma unroll
        for (int i = 0; i < STAGES; i++) {
            asm volatile("mbarrier.init.shared.b64 [%0], %1;"
                         :: "r"(mbfull + 8 * i), "r"(256u) : "memory");
            asm volatile("mbarrier.init.shared.b64 [%0], %1;"
                         :: "r"(mbempty + 8 * i), "r"(8u) : "memory");
        }
    }

    // stage km rows (m0..m0+4) as fp16
    __half* kms = reinterpret_cast<__half*>(smem + S_KMS);
#pragma unroll
    for (int e = tid; e < NM * DD; e += 256) {
        int mi = e >> 9, c = e & (DD - 1);
        kms[e] = __float2half_rn(kw[(m0 + mi) * DD + c]);
    }
    __syncthreads();   // mbarrier init + kms visible

    const __half* ltb = g_lt + (size_t)(b * TT + t0) * DD;
    const __half* rtb = g_rt + (size_t)b * TT * DD;

    const int wid  = tid >> 5;    // warp = 16 t-rows
    const int lane = tid & 31;
    const int wt   = wid;         // 0..7

    const uint32_t aoff = (uint32_t)(wt * 16 + (lane & 15)) * ROWB + (lane >> 4) * 16;
    const uint32_t boff = (uint32_t)((lane & 7) + ((lane >> 4) << 3)) * ROWB
                        + ((lane >> 3) & 1) * 16;
    const int c0 = (lane & 3) * 2;   // k column base of this thread's A frag elems

    float runmax[NM][2];
#pragma unroll
    for (int mi = 0; mi < NM; mi++) { runmax[mi][0] = -3.4e38f; runmax[mi][1] = -3.4e38f; }

    int fullp[STAGES]  = {0, 0, 0, 0};
    int emptyp[STAGES] = {1, 1, 1, 1};   // producer convention: first wait passes

    auto issue = [&](int st, int chunk) {
        const uint32_t sb = sbuf + (st & (STAGES - 1)) * STG_BYTES;
        const int k0 = st * KC;
#pragma unroll
        for (int i = 0; i < 4; i++) {   // A: 128 rows x 8 x 16B = 1024 chunks
            int c = tid + i * 256, row = c >> 3, sub = c & 7;
            CP16(sb + row * ROWB + sub * 16, ltb + row * DD + k0 + sub * 8);
        }
        {   // B: 32 rows x 8 x 16B = 256 chunks
            int row = tid >> 3, sub = tid & 7;
            CP16(sb + A_BYTES + row * ROWB + sub * 16,
                 rtb + (chunk * TN + row) * DD + k0 + sub * 8);
        }
    };

    auto produce = [&](int st, int chunk) {
        const int bfi = st & (STAGES - 1);
        MBWAIT(mbempty + 8 * bfi, emptyp[bfi]);
        emptyp[bfi] ^= 1;
        issue(st, chunk);
        // .noinc: completion-arrival counts against the init count (256)
        asm volatile("cp.async.mbarrier.arrive.noinc.shared.b64 [%0];"
                     :: "r"(mbfull + 8 * bfi) : "memory");
    };

    // fragment load for one k16 slice kk (0..3) of stage buffer sb
    auto ldfrag = [&](uint32_t sb, int kk, uint32_t* bf, uint32_t* af) {
        LDSM4(bf[0], bf[1], bf[2], bf[3], sb + A_BYTES + boff + kk * 32);
        LDSM4(bf[4], bf[5], bf[6], bf[7], sb + A_BYTES + boff + 16 * ROWB + kk * 32);
        LDSM4(af[0], af[1], af[2], af[3], sb + aoff + kk * 32);
    };

    for (int chunk = 0; chunk < NCHK; chunk++) {
        uint32_t acc[NM][4][2];          // [m][n-frag][reg] fp16x2
#pragma unroll
        for (int mi = 0; mi < NM; mi++)
#pragma unroll
            for (int ni = 0; ni < 4; ni++) {
                acc[mi][ni][0] = 0u; acc[mi][ni][1] = 0u;
            }

        // Prologue: 3 stages in flight
        produce(0, chunk);
        produce(1, chunk);
        produce(2, chunk);

#pragma unroll
        for (int ki = 0; ki < NST; ki++) {
            const int bfi = ki & (STAGES - 1);
            MBWAIT(mbfull + 8 * bfi, fullp[bfi]);
            fullp[bfi] ^= 1;
            const uint32_t sb = sbuf + bfi * STG_BYTES;

            uint32_t bfA[8], afA[4], bfB[8], afB[4];
            ldfrag(sb, 0, bfA, afA);
#pragma unroll
            for (int kk = 0; kk < 4; kk++) {
                uint32_t* bf = (kk & 1) ? bfB : bfA;
                uint32_t* af = (kk & 1) ? afB : afA;
                if (kk < 3) ldfrag(sb, kk + 1, (kk & 1) ? bfA : bfB,
                                               (kk & 1) ? afA : afB);
                const int kb = ki * KC + kk * 16;
#pragma unroll
                for (int mi = 0; mi < NM; mi++) {
                    const uint32_t kp0 =
                        *reinterpret_cast<const uint32_t*>(&kms[mi * DD + kb + c0]);
                    const uint32_t kp1 =
                        *reinterpret_cast<const uint32_t*>(&kms[mi * DD + kb + c0 + 8]);
                    uint32_t a0 = hmul2u(af[0], kp0);
                    uint32_t a1 = hmul2u(af[1], kp0);
                    uint32_t a2 = hmul2u(af[2], kp1);
                    uint32_t a3 = hmul2u(af[3], kp1);
#pragma unroll
                    for (int ni = 0; ni < 4; ni++)
                        MMA16816(acc[mi][ni][0], acc[mi][ni][1],
                                 a0, a1, a2, a3, bf[ni * 2], bf[ni * 2 + 1]);
                }
            }
            // this warp is done reading buffer bfi
            __syncwarp();
            if (lane == 0) {
                asm volatile("{\n\t.reg .b64 t;\n\t"
                             "mbarrier.arrive.shared.b64 t, [%0];\n\t}"
                             :: "r"(mbempty + 8 * bfi) : "memory");
            }
            if (ki + 3 < NST) produce(ki + 3, chunk);
        }

        // chunk max -> running max; vote on early exit (monotone-safe)
        bool pred = true;
#pragma unroll
        for (int mi = 0; mi < NM; mi++)
#pragma unroll
            for (int h = 0; h < 2; h++) {   // h=0: row g; h=1: row g+8
                __half2 v = *reinterpret_cast<__half2*>(&acc[mi][0][h]);
#pragma unroll
                for (int ni = 1; ni < 4; ni++)
                    v = __hmax2(v, *reinterpret_cast<__half2*>(&acc[mi][ni][h]));
                float fm = fmaxf(__low2float(v), __high2float(v));
                fm = fmaxf(fm, __shfl_xor_sync(0xffffffffu, fm, 1));
                fm = fmaxf(fm, __shfl_xor_sync(0xffffffffu, fm, 2));
                runmax[mi][h] = fmaxf(runmax[mi][h], fm);
                pred = pred && (runmax[mi][h] > THRESH);
            }
        int done = __syncthreads_and((int)pred);
        if (done) break;
    }

    // write: each 4-lane group holds maxes for rows wt*16 + h*8 + (lane>>2)
    if ((lane & 3) == 0) {
        const int g = lane >> 2;
#pragma unroll
        for (int mi = 0; mi < NM; mi++)
#pragma unroll
            for (int h = 0; h < 2; h++) {
                int row = wt * 16 + h * 8 + g;
                out[(size_t)(b * TT + t0 + row) * MPP + (m0 + mi)] =
                    tanhf(runmax[mi][h]);
            }
    }
}

// ---------------------------------------------------------------------------
// Launch: inputs: reps_lt[B,T,D] f32, reps_rt[B,T,D] f32, kernel[1,1,1,MP,D] f32.
// Output [B,T,MP] f32.
// ---------------------------------------------------------------------------
extern "C" void kernel_launch(void* const* d_in, const int* in_sizes, int n_in,
                              void* d_out, int out_size) {
    const float* lt = (const float*)d_in[0];
    const float* rt = (const float*)d_in[1];
    const float* kw = (const float*)d_in[2];
    float* out = (float*)d_out;

    const int n16 = (BB * TT * DD) / 16;  // 262,144 16-float units
    cvt_kernel<<<n16 / 256, 256>>>(lt, rt);

    cudaFuncSetAttribute(match_kernel,
                         cudaFuncAttributeMaxDynamicSharedMemorySize, S_TOTAL);
    dim3 grid(TT / TM, MPP / NM, BB);  // (2, 4, 32) = 256 CTAs
    match_kernel<<<grid, 256, S_TOTAL>>>(kw, out);
}

// round 12
// speedup vs baseline: 1.0795x; 1.0795x over previous
#include <cuda_runtime.h>
#include <cuda_fp16.h>
#include <cstdint>

// Problem constants
#define BB  32
#define TT  256
#define DD  512
#define MPP 20

constexpr int TM     = 128;            // CTA t rows
constexpr int TN     = 32;             // s cols per verified chunk
constexpr int NCHK   = TT / TN;        // 8 s-chunks
constexpr int NM     = 5;              // m-planes per CTA (20 = 4 groups of 5)
constexpr int KC     = 64;             // k per pipeline stage (4 x k16)
constexpr int NST    = DD / KC;        // 8 stages
constexpr int STAGES = 4;              // buffer ring depth
constexpr int ROWB   = 144;            // smem row bytes: 128B data + 16B pad
constexpr int A_BYTES   = TM * ROWB;              // 18432
constexpr int B_BYTES   = TN * ROWB;              // 4608
constexpr int STG_BYTES = A_BYTES + B_BYTES;      // 23040

constexpr int S_KMS  = 0;              // 5*512 halves = 5120 B
constexpr int S_MBAR = 5120;           // 8 x 8B mbarriers (4 full + 4 empty)
constexpr int S_BUF  = 5248;           // 128B aligned
constexpr int S_TOTAL = S_BUF + STAGES * STG_BYTES;  // 97408 B

constexpr float THRESH = 10.0f;        // tanh(10) = 1 - 4.1e-9; monotone-safe exit

// static device scratch (allocation-free per harness rules)
__device__ __half g_lt[BB * TT * DD];
__device__ __half g_rt0[BB * TN * DD];   // only s-chunk 0 of rt, pre-converted

static __device__ __forceinline__ uint32_t s2u(const void* p) {
    return (uint32_t)__cvta_generic_to_shared(p);
}

#define CP16(dst, src) \
    asm volatile("cp.async.cg.shared.global [%0], [%1], 16;" :: "r"(dst), "l"(src))

#define LDSM4(r0, r1, r2, r3, addr)                                              \
    asm volatile("ldmatrix.sync.aligned.m8n8.x4.shared.b16 {%0,%1,%2,%3}, [%4];" \
                 : "=r"(r0), "=r"(r1), "=r"(r2), "=r"(r3) : "r"(addr))

#define MMA16816(d0, d1, a0, a1, a2, a3, b0, b1)                                  \
    asm volatile("mma.sync.aligned.m16n8k16.row.col.f16.f16.f16.f16 "             \
                 "{%0,%1},{%2,%3,%4,%5},{%6,%7},{%0,%1};"                         \
                 : "+r"(d0), "+r"(d1)                                             \
                 : "r"(a0), "r"(a1), "r"(a2), "r"(a3), "r"(b0), "r"(b1))

// spin (with suspend hint) until the mbarrier phase with given parity completes
#define MBWAIT(addr, ph)                                                          \
    asm volatile("{\n\t.reg .pred P;\n\t"                                         \
                 "MBW%=:\n\t"                                                     \
                 "mbarrier.try_wait.parity.shared.b64 P, [%0], %1, 0x989680;\n\t" \
                 "@!P bra MBW%=;\n\t}"                                            \
                 :: "r"(addr), "r"(ph) : "memory")

static __device__ __forceinline__ uint32_t hmul2u(uint32_t a, uint32_t b) {
    __half2 r = __hmul2(*reinterpret_cast<__half2*>(&a),
                        *reinterpret_cast<__half2*>(&b));
    return *reinterpret_cast<uint32_t*>(&r);
}

// ---------------------------------------------------------------------------
// Kernel 1: convert lt (all) + rt s-chunk-0 rows to fp16.
// Unit = 16 consecutive floats. Units 0..NLT-1 -> lt; NLT.. -> rt chunk 0.
// ---------------------------------------------------------------------------
constexpr int NLT  = BB * TT * DD / 16;   // 262144
constexpr int NRT0 = BB * TN * DD / 16;   // 32768
constexpr int NCVT = NLT + NRT0;          // 294912

__global__ void cvt_kernel(const float* __restrict__ lt, const float* __restrict__ rt) {
    int i = blockIdx.x * blockDim.x + threadIdx.x;
    const float4* src;
    __half* dst;
    if (i < NLT) {
        src = reinterpret_cast<const float4*>(lt) + (size_t)i * 4;
        dst = g_lt + (size_t)i * 16;
    } else {
        int j = i - NLT;                       // unit within rt chunk-0 view
        int per_b = TN * DD / 16;              // 1024 units per b
        int b = j / per_b, r = j % per_b;      // r covers rows 0..31 contiguously
        src = reinterpret_cast<const float4*>(rt + (size_t)b * TT * DD) + (size_t)r * 4;
        dst = g_rt0 + ((size_t)b * TN * DD + (size_t)r * 16);
    }
    float4 a[4];
#pragma unroll
    for (int j = 0; j < 4; j++) a[j] = src[j];
    uint32_t w[8];
#pragma unroll
    for (int j = 0; j < 4; j++) {
        __half2 h0 = __floats2half2_rn(a[j].x, a[j].y);
        __half2 h1 = __floats2half2_rn(a[j].z, a[j].w);
        w[j * 2]     = *reinterpret_cast<uint32_t*>(&h0);
        w[j * 2 + 1] = *reinterpret_cast<uint32_t*>(&h1);
    }
    uint4* d = reinterpret_cast<uint4*>(dst);
    d[0] = make_uint4(w[0], w[1], w[2], w[3]);
    d[1] = make_uint4(w[4], w[5], w[6], w[7]);
}

// ---------------------------------------------------------------------------
// Kernel 2: one CTA = (b, t-tile 128, 5 m-planes). s-chunk 0 via the
// mbarrier cp.async pipeline (B from pre-converted g_rt0); rare fallback
// chunks 1..7 via a synchronous path that converts B from the original f32
// rt in-kernel (identical __float2half_rn rounding -> bit-identical scores).
// 8 warps, warp tile 16t x 32s x 5m, fp16 HMMA fp16-acc, km in registers.
// ---------------------------------------------------------------------------
__global__ __launch_bounds__(256, 2)
void match_kernel(const float* __restrict__ kw, const float* __restrict__ rtf,
                  float* __restrict__ out) {
    extern __shared__ __align__(128) char smem[];
    const int tid = threadIdx.x;
    const int b   = blockIdx.z;
    const int m0  = blockIdx.y * NM;
    const int t0  = blockIdx.x * TM;
    const uint32_t sbase   = s2u(smem);
    const uint32_t sbuf    = sbase + S_BUF;
    const uint32_t mbfull  = sbase + S_MBAR;        // 4 x 8B
    const uint32_t mbempty = sbase + S_MBAR + 32;   // 4 x 8B

    if (tid == 0) {
#pragma unroll
        for (int i = 0; i < STAGES; i++) {
            asm volatile("mbarrier.init.shared.b64 [%0], %1;"
                         :: "r"(mbfull + 8 * i), "r"(256u) : "memory");
            asm volatile("mbarrier.init.shared.b64 [%0], %1;"
                         :: "r"(mbempty + 8 * i), "r"(8u) : "memory");
        }
    }

    // stage km rows (m0..m0+4) as fp16
    __half* kms = reinterpret_cast<__half*>(smem + S_KMS);
#pragma unroll
    for (int e = tid; e < NM * DD; e += 256) {
        int mi = e >> 9, c = e & (DD - 1);
        kms[e] = __float2half_rn(kw[(m0 + mi) * DD + c]);
    }
    __syncthreads();   // mbarrier init + kms visible

    const __half* ltb  = g_lt  + (size_t)(b * TT + t0) * DD;
    const __half* rt0b = g_rt0 + (size_t)b * TN * DD;
    const float*  rtfb = rtf   + (size_t)b * TT * DD;

    const int wid  = tid >> 5;    // warp = 16 t-rows
    const int lane = tid & 31;
    const int wt   = wid;         // 0..7

    const uint32_t aoff = (uint32_t)(wt * 16 + (lane & 15)) * ROWB + (lane >> 4) * 16;
    const uint32_t boff = (uint32_t)((lane & 7) + ((lane >> 4) << 3)) * ROWB
                        + ((lane >> 3) & 1) * 16;
    const int c0 = (lane & 3) * 2;

    float runmax[NM][2];
#pragma unroll
    for (int mi = 0; mi < NM; mi++) { runmax[mi][0] = -3.4e38f; runmax[mi][1] = -3.4e38f; }

    int fullp[STAGES]  = {0, 0, 0, 0};
    int emptyp[STAGES] = {1, 1, 1, 1};

    auto issueA = [&](uint32_t sb, int st) {
        const int k0 = st * KC;
#pragma unroll
        for (int i = 0; i < 4; i++) {   // A: 128 rows x 8 x 16B = 1024 chunks
            int c = tid + i * 256, row = c >> 3, sub = c & 7;
            CP16(sb + row * ROWB + sub * 16, ltb + row * DD + k0 + sub * 8);
        }
    };

    auto produce = [&](int st) {        // chunk-0 producer (B from g_rt0)
        const int bfi = st & (STAGES - 1);
        const uint32_t sb = sbuf + bfi * STG_BYTES;
        MBWAIT(mbempty + 8 * bfi, emptyp[bfi]);
        emptyp[bfi] ^= 1;
        issueA(sb, st);
        {   // B: 32 rows x 8 x 16B = 256 chunks
            int row = tid >> 3, sub = tid & 7;
            CP16(sb + A_BYTES + row * ROWB + sub * 16,
                 rt0b + row * DD + st * KC + sub * 8);
        }
        asm volatile("cp.async.mbarrier.arrive.noinc.shared.b64 [%0];"
                     :: "r"(mbfull + 8 * bfi) : "memory");
    };

    auto ldfrag = [&](uint32_t sb, int kk, uint32_t* bf, uint32_t* af) {
        LDSM4(bf[0], bf[1], bf[2], bf[3], sb + A_BYTES + boff + kk * 32);
        LDSM4(bf[4], bf[5], bf[6], bf[7], sb + A_BYTES + boff + 16 * ROWB + kk * 32);
        LDSM4(af[0], af[1], af[2], af[3], sb + aoff + kk * 32);
    };

    uint32_t acc[NM][4][2];
    auto clear_acc = [&]() {
#pragma unroll
        for (int mi = 0; mi < NM; mi++)
#pragma unroll
            for (int ni = 0; ni < 4; ni++) { acc[mi][ni][0] = 0u; acc[mi][ni][1] = 0u; }
    };

    auto compute = [&](uint32_t sb, int ki) {
        uint32_t bfA[8], afA[4], bfB[8], afB[4];
        ldfrag(sb, 0, bfA, afA);
#pragma unroll
        for (int kk = 0; kk < 4; kk++) {
            uint32_t* bf = (kk & 1) ? bfB : bfA;
            uint32_t* af = (kk & 1) ? afB : afA;
            if (kk < 3) ldfrag(sb, kk + 1, (kk & 1) ? bfA : bfB, (kk & 1) ? afA : afB);
            const int kb = ki * KC + kk * 16;
#pragma unroll
            for (int mi = 0; mi < NM; mi++) {
                const uint32_t kp0 =
                    *reinterpret_cast<const uint32_t*>(&kms[mi * DD + kb + c0]);
                const uint32_t kp1 =
                    *reinterpret_cast<const uint32_t*>(&kms[mi * DD + kb + c0 + 8]);
                uint32_t a0 = hmul2u(af[0], kp0);
                uint32_t a1 = hmul2u(af[1], kp0);
                uint32_t a2 = hmul2u(af[2], kp1);
                uint32_t a3 = hmul2u(af[3], kp1);
#pragma unroll
                for (int ni = 0; ni < 4; ni++)
                    MMA16816(acc[mi][ni][0], acc[mi][ni][1],
                             a0, a1, a2, a3, bf[ni * 2], bf[ni * 2 + 1]);
            }
        }
    };

    // returns true if every row's running max clears THRESH (monotone-safe)
    auto reduce_vote = [&]() -> int {
        bool pred = true;
#pragma unroll
        for (int mi = 0; mi < NM; mi++)
#pragma unroll
            for (int h = 0; h < 2; h++) {
                __half2 v = *reinterpret_cast<__half2*>(&acc[mi][0][h]);
#pragma unroll
                for (int ni = 1; ni < 4; ni++)
                    v = __hmax2(v, *reinterpret_cast<__half2*>(&acc[mi][ni][h]));
                float fm = fmaxf(__low2float(v), __high2float(v));
                fm = fmaxf(fm, __shfl_xor_sync(0xffffffffu, fm, 1));
                fm = fmaxf(fm, __shfl_xor_sync(0xffffffffu, fm, 2));
                runmax[mi][h] = fmaxf(runmax[mi][h], fm);
                pred = pred && (runmax[mi][h] > THRESH);
            }
        return __syncthreads_and((int)pred);
    };

    // ---- chunk 0: pipelined fast path ----
    clear_acc();
    produce(0); produce(1); produce(2);
#pragma unroll
    for (int ki = 0; ki < NST; ki++) {
        const int bfi = ki & (STAGES - 1);
        MBWAIT(mbfull + 8 * bfi, fullp[bfi]);
        fullp[bfi] ^= 1;
        if (ki + 3 < NST) produce(ki + 3);   // prefetch before compute burst
        compute(sbuf + bfi * STG_BYTES, ki);
        __syncwarp();
        if (lane == 0) {
            asm volatile("{\n\t.reg .b64 t;\n\t"
                         "mbarrier.arrive.shared.b64 t, [%0];\n\t}"
                         :: "r"(mbempty + 8 * bfi) : "memory");
        }
    }
    int done = reduce_vote();

    // ---- chunks 1..7: rare exact fallback (B from f32 rt, converted here) ----
    if (!done) {
        for (int chunk = 1; chunk < NCHK; chunk++) {
            clear_acc();
            for (int ki = 0; ki < NST; ki++) {
                const uint32_t sb = sbuf + (ki & (STAGES - 1)) * STG_BYTES;
                issueA(sb, ki);
                asm volatile("cp.async.commit_group;" ::: "memory");
                {   // B: one 16B f16 chunk per thread, converted from f32
                    int row = tid >> 3, sub = tid & 7;
                    const float* s = rtfb + (size_t)(chunk * TN + row) * DD
                                   + ki * KC + sub * 8;
                    float4 f0 = *reinterpret_cast<const float4*>(s);
                    float4 f1 = *reinterpret_cast<const float4*>(s + 4);
                    uint32_t w[4];
                    __half2 h;
                    h = __floats2half2_rn(f0.x, f0.y); w[0] = *reinterpret_cast<uint32_t*>(&h);
                    h = __floats2half2_rn(f0.z, f0.w); w[1] = *reinterpret_cast<uint32_t*>(&h);
                    h = __floats2half2_rn(f1.x, f1.y); w[2] = *reinterpret_cast<uint32_t*>(&h);
                    h = __floats2half2_rn(f1.z, f1.w); w[3] = *reinterpret_cast<uint32_t*>(&h);
                    uint32_t dstp = sb + A_BYTES + row * ROWB + sub * 16;
                    asm volatile("st.shared.v4.b32 [%0], {%1,%2,%3,%4};"
                                 :: "r"(dstp), "r"(w[0]), "r"(w[1]), "r"(w[2]), "r"(w[3])
                                 : "memory");
                }
                asm volatile("cp.async.wait_all;" ::: "memory");
                __syncthreads();
                compute(sb, ki);
                __syncthreads();
            }
            done = reduce_vote();
            if (done) break;
        }
    }

    // write: each 4-lane group holds maxes for rows wt*16 + h*8 + (lane>>2)
    if ((lane & 3) == 0) {
        const int g = lane >> 2;
#pragma unroll
        for (int mi = 0; mi < NM; mi++)
#pragma unroll
            for (int h = 0; h < 2; h++) {
                int row = wt * 16 + h * 8 + g;
                out[(size_t)(b * TT + t0 + row) * MPP + (m0 + mi)] =
                    tanhf(runmax[mi][h]);
            }
    }
}

// ---------------------------------------------------------------------------
// Launch: inputs: reps_lt[B,T,D] f32, reps_rt[B,T,D] f32, kernel[1,1,1,MP,D] f32.
// Output [B,T,MP] f32.
// ---------------------------------------------------------------------------
extern "C" void kernel_launch(void* const* d_in, const int* in_sizes, int n_in,
                              void* d_out, int out_size) {
    const float* lt = (const float*)d_in[0];
    const float* rt = (const float*)d_in[1];
    const float* kw = (const float*)d_in[2];
    float* out = (float*)d_out;

    cvt_kernel<<<NCVT / 256, 256>>>(lt, rt);

    cudaFuncSetAttribute(match_kernel,
                         cudaFuncAttributeMaxDynamicSharedMemorySize, S_TOTAL);
    dim3 grid(TT / TM, MPP / NM, BB);  // (2, 4, 32) = 256 CTAs
    match_kernel<<<grid, 256, S_TOTAL>>>(kw, rt, out);
}

// round 13
// speedup vs baseline: 1.0906x; 1.0102x over previous
#include <cuda_runtime.h>
#include <cuda_fp16.h>
#include <cstdint>

// Problem constants
#define BB  32
#define TT  256
#define DD  512
#define MPP 20

constexpr int TM     = 64;             // CTA t rows
constexpr int TN     = 32;             // s cols per verified chunk
constexpr int NCHK   = TT / TN;        // 8 s-chunks
constexpr int NM     = 5;              // m-planes per CTA (20 = 4 groups of 5)
constexpr int KC     = 64;             // k per pipeline stage (4 x k16)
constexpr int NST    = DD / KC;        // 8 stages
constexpr int STAGES = 3;              // buffer ring depth (produce-ahead 2)
constexpr int NTHR   = 128;            // 4 warps -> one per SMSP
constexpr int ROWB   = 144;            // smem row bytes: 128B data + 16B pad
constexpr int A_BYTES   = TM * ROWB;              // 9216
constexpr int B_BYTES   = TN * ROWB;              // 4608
constexpr int STG_BYTES = A_BYTES + B_BYTES;      // 13824

constexpr int S_KMS  = 0;              // 5*512 halves = 5120 B
constexpr int S_MBAR = 5120;           // 6 x 8B mbarriers (3 full + 3 empty)
constexpr int S_BUF  = 5248;           // 128B aligned
constexpr int S_TOTAL = S_BUF + STAGES * STG_BYTES;  // 46720 B

constexpr float THRESH = 10.0f;        // tanh(10) = 1 - 4.1e-9; monotone-safe exit

// static device scratch (allocation-free per harness rules)
__device__ __half g_lt[BB * TT * DD];
__device__ __half g_rt0[BB * TN * DD];   // only s-chunk 0 of rt, pre-converted

static __device__ __forceinline__ uint32_t s2u(const void* p) {
    return (uint32_t)__cvta_generic_to_shared(p);
}

#define CP16(dst, src) \
    asm volatile("cp.async.cg.shared.global [%0], [%1], 16;" :: "r"(dst), "l"(src))

#define LDSM4(r0, r1, r2, r3, addr)                                              \
    asm volatile("ldmatrix.sync.aligned.m8n8.x4.shared.b16 {%0,%1,%2,%3}, [%4];" \
                 : "=r"(r0), "=r"(r1), "=r"(r2), "=r"(r3) : "r"(addr))

#define MMA16816(d0, d1, a0, a1, a2, a3, b0, b1)                                  \
    asm volatile("mma.sync.aligned.m16n8k16.row.col.f16.f16.f16.f16 "             \
                 "{%0,%1},{%2,%3,%4,%5},{%6,%7},{%0,%1};"                         \
                 : "+r"(d0), "+r"(d1)                                             \
                 : "r"(a0), "r"(a1), "r"(a2), "r"(a3), "r"(b0), "r"(b1))

// spin (with suspend hint) until the mbarrier phase with given parity completes
#define MBWAIT(addr, ph)                                                          \
    asm volatile("{\n\t.reg .pred P;\n\t"                                         \
                 "MBW%=:\n\t"                                                     \
                 "mbarrier.try_wait.parity.shared.b64 P, [%0], %1, 0x989680;\n\t" \
                 "@!P bra MBW%=;\n\t}"                                            \
                 :: "r"(addr), "r"(ph) : "memory")

static __device__ __forceinline__ uint32_t hmul2u(uint32_t a, uint32_t b) {
    __half2 r = __hmul2(*reinterpret_cast<__half2*>(&a),
                        *reinterpret_cast<__half2*>(&b));
    return *reinterpret_cast<uint32_t*>(&r);
}

// ---------------------------------------------------------------------------
// Kernel 1: convert lt (all) + rt s-chunk-0 rows to fp16.
// ---------------------------------------------------------------------------
constexpr int NLT  = BB * TT * DD / 16;   // 262144
constexpr int NRT0 = BB * TN * DD / 16;   // 32768
constexpr int NCVT = NLT + NRT0;          // 294912

__global__ void cvt_kernel(const float* __restrict__ lt, const float* __restrict__ rt) {
    int i = blockIdx.x * blockDim.x + threadIdx.x;
    const float4* src;
    __half* dst;
    if (i < NLT) {
        src = reinterpret_cast<const float4*>(lt) + (size_t)i * 4;
        dst = g_lt + (size_t)i * 16;
    } else {
        int j = i - NLT;                       // unit within rt chunk-0 view
        int per_b = TN * DD / 16;              // 1024 units per b
        int b = j / per_b, r = j % per_b;      // r covers rows 0..31 contiguously
        src = reinterpret_cast<const float4*>(rt + (size_t)b * TT * DD) + (size_t)r * 4;
        dst = g_rt0 + ((size_t)b * TN * DD + (size_t)r * 16);
    }
    float4 a[4];
#pragma unroll
    for (int j = 0; j < 4; j++) a[j] = src[j];
    uint32_t w[8];
#pragma unroll
    for (int j = 0; j < 4; j++) {
        __half2 h0 = __floats2half2_rn(a[j].x, a[j].y);
        __half2 h1 = __floats2half2_rn(a[j].z, a[j].w);
        w[j * 2]     = *reinterpret_cast<uint32_t*>(&h0);
        w[j * 2 + 1] = *reinterpret_cast<uint32_t*>(&h1);
    }
    uint4* d = reinterpret_cast<uint4*>(dst);
    d[0] = make_uint4(w[0], w[1], w[2], w[3]);
    d[1] = make_uint4(w[4], w[5], w[6], w[7]);
}

// ---------------------------------------------------------------------------
// Kernel 2: one CTA = (b, t-tile 64, 5 m-planes), 128 threads (one warp per
// SMSP). 4 CTAs/SM: each SMSP hosts 4 warps from 4 INDEPENDENT CTAs, so
// barrier waits in one CTA are covered by unrelated warps. s-chunk 0 via
// mbarrier cp.async pipeline (B from g_rt0); rare exact fallback converts B
// from f32 rt in-kernel (identical rounding). fp16 HMMA fp16-acc.
// ---------------------------------------------------------------------------
__global__ __launch_bounds__(NTHR, 4)
void match_kernel(const float* __restrict__ kw, const float* __restrict__ rtf,
                  float* __restrict__ out) {
    extern __shared__ __align__(128) char smem[];
    const int tid = threadIdx.x;
    const int b   = blockIdx.z;
    const int m0  = blockIdx.y * NM;
    const int t0  = blockIdx.x * TM;
    const uint32_t sbase   = s2u(smem);
    const uint32_t sbuf    = sbase + S_BUF;
    const uint32_t mbfull  = sbase + S_MBAR;        // 3 x 8B
    const uint32_t mbempty = sbase + S_MBAR + 24;   // 3 x 8B

    if (tid == 0) {
#pragma unroll
        for (int i = 0; i < STAGES; i++) {
            asm volatile("mbarrier.init.shared.b64 [%0], %1;"
                         :: "r"(mbfull + 8 * i), "r"((uint32_t)NTHR) : "memory");
            asm volatile("mbarrier.init.shared.b64 [%0], %1;"
                         :: "r"(mbempty + 8 * i), "r"(4u) : "memory");
        }
    }

    // stage km rows (m0..m0+4) as fp16
    __half* kms = reinterpret_cast<__half*>(smem + S_KMS);
#pragma unroll
    for (int e = tid; e < NM * DD; e += NTHR) {
        int mi = e >> 9, c = e & (DD - 1);
        kms[e] = __float2half_rn(kw[(m0 + mi) * DD + c]);
    }
    __syncthreads();   // mbarrier init + kms visible

    const __half* ltb  = g_lt  + (size_t)(b * TT + t0) * DD;
    const __half* rt0b = g_rt0 + (size_t)b * TN * DD;
    const float*  rtfb = rtf   + (size_t)b * TT * DD;

    const int wid  = tid >> 5;    // warp = 16 t-rows (4 warps x 16 = 64)
    const int lane = tid & 31;
    const int wt   = wid;         // 0..3

    const uint32_t aoff = (uint32_t)(wt * 16 + (lane & 15)) * ROWB + (lane >> 4) * 16;
    const uint32_t boff = (uint32_t)((lane & 7) + ((lane >> 4) << 3)) * ROWB
                        + ((lane >> 3) & 1) * 16;
    const int c0 = (lane & 3) * 2;

    float runmax[NM][2];
#pragma unroll
    for (int mi = 0; mi < NM; mi++) { runmax[mi][0] = -3.4e38f; runmax[mi][1] = -3.4e38f; }

    int fullp[STAGES]  = {0, 0, 0};
    int emptyp[STAGES] = {1, 1, 1};

    auto issueA = [&](uint32_t sb, int st) {
        const int k0 = st * KC;
#pragma unroll
        for (int i = 0; i < 4; i++) {   // A: 64 rows x 8 x 16B = 512 chunks
            int c = tid + i * NTHR, row = c >> 3, sub = c & 7;
            CP16(sb + row * ROWB + sub * 16, ltb + row * DD + k0 + sub * 8);
        }
    };

    auto produce = [&](int st) {        // chunk-0 producer (B from g_rt0)
        const int bfi = st % STAGES;
        const uint32_t sb = sbuf + bfi * STG_BYTES;
        MBWAIT(mbempty + 8 * bfi, emptyp[bfi]);
        emptyp[bfi] ^= 1;
        issueA(sb, st);
#pragma unroll
        for (int i = 0; i < 2; i++) {   // B: 32 rows x 8 x 16B = 256 chunks
            int c = tid + i * NTHR, row = c >> 3, sub = c & 7;
            CP16(sb + A_BYTES + row * ROWB + sub * 16,
                 rt0b + row * DD + st * KC + sub * 8);
        }
        asm volatile("cp.async.mbarrier.arrive.noinc.shared.b64 [%0];"
                     :: "r"(mbfull + 8 * bfi) : "memory");
    };

    auto ldfrag = [&](uint32_t sb, int kk, uint32_t* bf, uint32_t* af) {
        LDSM4(bf[0], bf[1], bf[2], bf[3], sb + A_BYTES + boff + kk * 32);
        LDSM4(bf[4], bf[5], bf[6], bf[7], sb + A_BYTES + boff + 16 * ROWB + kk * 32);
        LDSM4(af[0], af[1], af[2], af[3], sb + aoff + kk * 32);
    };

    uint32_t acc[NM][4][2];
    auto clear_acc = [&]() {
#pragma unroll
        for (int mi = 0; mi < NM; mi++)
#pragma unroll
            for (int ni = 0; ni < 4; ni++) { acc[mi][ni][0] = 0u; acc[mi][ni][1] = 0u; }
    };

    auto compute = [&](uint32_t sb, int ki) {
        uint32_t bfA[8], afA[4], bfB[8], afB[4];
        ldfrag(sb, 0, bfA, afA);
#pragma unroll
        for (int kk = 0; kk < 4; kk++) {
            uint32_t* bf = (kk & 1) ? bfB : bfA;
            uint32_t* af = (kk & 1) ? afB : afA;
            if (kk < 3) ldfrag(sb, kk + 1, (kk & 1) ? bfA : bfB, (kk & 1) ? afA : afB);
            const int kb = ki * KC + kk * 16;
#pragma unroll
            for (int mi = 0; mi < NM; mi++) {
                const uint32_t kp0 =
                    *reinterpret_cast<const uint32_t*>(&kms[mi * DD + kb + c0]);
                const uint32_t kp1 =
                    *reinterpret_cast<const uint32_t*>(&kms[mi * DD + kb + c0 + 8]);
                uint32_t a0 = hmul2u(af[0], kp0);
                uint32_t a1 = hmul2u(af[1], kp0);
                uint32_t a2 = hmul2u(af[2], kp1);
                uint32_t a3 = hmul2u(af[3], kp1);
#pragma unroll
                for (int ni = 0; ni < 4; ni++)
                    MMA16816(acc[mi][ni][0], acc[mi][ni][1],
                             a0, a1, a2, a3, bf[ni * 2], bf[ni * 2 + 1]);
            }
        }
    };

    // returns true if every row's running max clears THRESH (monotone-safe)
    auto reduce_vote = [&]() -> int {
        bool pred = true;
#pragma unroll
        for (int mi = 0; mi < NM; mi++)
#pragma unroll
            for (int h = 0; h < 2; h++) {
                __half2 v = *reinterpret_cast<__half2*>(&acc[mi][0][h]);
#pragma unroll
                for (int ni = 1; ni < 4; ni++)
                    v = __hmax2(v, *reinterpret_cast<__half2*>(&acc[mi][ni][h]));
                float fm = fmaxf(__low2float(v), __high2float(v));
                fm = fmaxf(fm, __shfl_xor_sync(0xffffffffu, fm, 1));
                fm = fmaxf(fm, __shfl_xor_sync(0xffffffffu, fm, 2));
                runmax[mi][h] = fmaxf(runmax[mi][h], fm);
                pred = pred && (runmax[mi][h] > THRESH);
            }
        return __syncthreads_and((int)pred);
    };

    // ---- chunk 0: pipelined fast path (ring of 3, produce-ahead 2) ----
    clear_acc();
    produce(0); produce(1);
#pragma unroll
    for (int ki = 0; ki < NST; ki++) {
        const int bfi = ki % STAGES;
        MBWAIT(mbfull + 8 * bfi, fullp[bfi]);
        fullp[bfi] ^= 1;
        if (ki + 2 < NST) produce(ki + 2);
        compute(sbuf + bfi * STG_BYTES, ki);
        __syncwarp();
        if (lane == 0) {
            asm volatile("{\n\t.reg .b64 t;\n\t"
                         "mbarrier.arrive.shared.b64 t, [%0];\n\t}"
                         :: "r"(mbempty + 8 * bfi) : "memory");
        }
    }
    int done = reduce_vote();

    // ---- chunks 1..7: rare exact fallback (B from f32 rt, converted here) ----
    if (!done) {
        for (int chunk = 1; chunk < NCHK; chunk++) {
            clear_acc();
            for (int ki = 0; ki < NST; ki++) {
                const uint32_t sb = sbuf + (ki % STAGES) * STG_BYTES;
                issueA(sb, ki);
                asm volatile("cp.async.commit_group;" ::: "memory");
#pragma unroll
                for (int i = 0; i < 2; i++) {   // B: f32 -> f16 in regs
                    int c = tid + i * NTHR, row = c >> 3, sub = c & 7;
                    const float* s = rtfb + (size_t)(chunk * TN + row) * DD
                                   + ki * KC + sub * 8;
                    float4 f0 = *reinterpret_cast<const float4*>(s);
                    float4 f1 = *reinterpret_cast<const float4*>(s + 4);
                    uint32_t w[4];
                    __half2 h;
                    h = __floats2half2_rn(f0.x, f0.y); w[0] = *reinterpret_cast<uint32_t*>(&h);
                    h = __floats2half2_rn(f0.z, f0.w); w[1] = *reinterpret_cast<uint32_t*>(&h);
                    h = __floats2half2_rn(f1.x, f1.y); w[2] = *reinterpret_cast<uint32_t*>(&h);
                    h = __floats2half2_rn(f1.z, f1.w); w[3] = *reinterpret_cast<uint32_t*>(&h);
                    uint32_t dstp = sb + A_BYTES + row * ROWB + sub * 16;
                    asm volatile("st.shared.v4.b32 [%0], {%1,%2,%3,%4};"
                                 :: "r"(dstp), "r"(w[0]), "r"(w[1]), "r"(w[2]), "r"(w[3])
                                 : "memory");
                }
                asm volatile("cp.async.wait_all;" ::: "memory");
                __syncthreads();
                compute(sb, ki);
                __syncthreads();
            }
            done = reduce_vote();
            if (done) break;
        }
    }

    // write: each 4-lane group holds maxes for rows wt*16 + h*8 + (lane>>2)
    if ((lane & 3) == 0) {
        const int g = lane >> 2;
#pragma unroll
        for (int mi = 0; mi < NM; mi++)
#pragma unroll
            for (int h = 0; h < 2; h++) {
                int row = wt * 16 + h * 8 + g;
                out[(size_t)(b * TT + t0 + row) * MPP + (m0 + mi)] =
                    tanhf(runmax[mi][h]);
            }
    }
}

// ---------------------------------------------------------------------------
// Launch: inputs: reps_lt[B,T,D] f32, reps_rt[B,T,D] f32, kernel[1,1,1,MP,D] f32.
// Output [B,T,MP] f32.
// ---------------------------------------------------------------------------
extern "C" void kernel_launch(void* const* d_in, const int* in_sizes, int n_in,
                              void* d_out, int out_size) {
    const float* lt = (const float*)d_in[0];
    const float* rt = (const float*)d_in[1];
    const float* kw = (const float*)d_in[2];
    float* out = (float*)d_out;

    cvt_kernel<<<NCVT / 256, 256>>>(lt, rt);

    cudaFuncSetAttribute(match_kernel,
                         cudaFuncAttributeMaxDynamicSharedMemorySize, S_TOTAL);
    dim3 grid(TT / TM, MPP / NM, BB);  // (4, 4, 32) = 512 CTAs
    match_kernel<<<grid, NTHR, S_TOTAL>>>(kw, rt, out);
}

// round 14
// speedup vs baseline: 1.0920x; 1.0013x over previous
#include <cuda_runtime.h>
#include <cuda_fp16.h>
#include <cstdint>

// Problem constants
#define BB  32
#define TT  256
#define DD  512
#define MPP 20

constexpr int TM     = 64;             // CTA t rows
constexpr int TN     = 32;             // s cols per verified chunk
constexpr int NCHK   = TT / TN;        // 8 s-chunks
constexpr int NM     = 5;              // m-planes per CTA (20 = 4 groups of 5)
constexpr int KC     = 64;             // k per pipeline stage (4 x k16)
constexpr int NST    = DD / KC;        // 8 stages
constexpr int STAGES = 2;              // buffer ring depth (produce-ahead 1)
constexpr int NTHR   = 128;            // 4 warps -> one per SMSP
constexpr int ROWA   = 272;            // A row bytes (f32): 256B data + 16B pad
constexpr int ROWB   = 144;            // B row bytes (f16): 128B data + 16B pad
constexpr int A_BYTES   = TM * ROWA;              // 17408
constexpr int B_BYTES   = TN * ROWB;              // 4608
constexpr int STG_BYTES = A_BYTES + B_BYTES;      // 22016

constexpr int S_KMS  = 0;              // 5*512 halves = 5120 B
constexpr int S_MBAR = 5120;           // 4 x 8B mbarriers (2 full + 2 empty)
constexpr int S_BUF  = 5248;           // 128B aligned
constexpr int S_TOTAL = S_BUF + STAGES * STG_BYTES;  // 49280 B

constexpr float THRESH = 10.0f;        // tanh(10) = 1 - 4.1e-9; monotone-safe exit

// static device scratch (allocation-free per harness rules)
__device__ __half g_rt0[BB * TN * DD];   // only s-chunk 0 of rt, pre-converted

static __device__ __forceinline__ uint32_t s2u(const void* p) {
    return (uint32_t)__cvta_generic_to_shared(p);
}

#define CP16(dst, src) \
    asm volatile("cp.async.cg.shared.global [%0], [%1], 16;" :: "r"(dst), "l"(src))

#define LDSM4(r0, r1, r2, r3, addr)                                              \
    asm volatile("ldmatrix.sync.aligned.m8n8.x4.shared.b16 {%0,%1,%2,%3}, [%4];" \
                 : "=r"(r0), "=r"(r1), "=r"(r2), "=r"(r3) : "r"(addr))

#define MMA16816(d0, d1, a0, a1, a2, a3, b0, b1)                                  \
    asm volatile("mma.sync.aligned.m16n8k16.row.col.f16.f16.f16.f16 "             \
                 "{%0,%1},{%2,%3,%4,%5},{%6,%7},{%0,%1};"                         \
                 : "+r"(d0), "+r"(d1)                                             \
                 : "r"(a0), "r"(a1), "r"(a2), "r"(a3), "r"(b0), "r"(b1))

// spin (with suspend hint) until the mbarrier phase with given parity completes
#define MBWAIT(addr, ph)                                                          \
    asm volatile("{\n\t.reg .pred P;\n\t"                                         \
                 "MBW%=:\n\t"                                                     \
                 "mbarrier.try_wait.parity.shared.b64 P, [%0], %1, 0x989680;\n\t" \
                 "@!P bra MBW%=;\n\t}"                                            \
                 :: "r"(addr), "r"(ph) : "memory")

static __device__ __forceinline__ uint32_t hmul2u(uint32_t a, uint32_t b) {
    __half2 r = __hmul2(*reinterpret_cast<__half2*>(&a),
                        *reinterpret_cast<__half2*>(&b));
    return *reinterpret_cast<uint32_t*>(&r);
}
static __device__ __forceinline__ uint32_t f2h2(float lo, float hi) {
    __half2 h = __floats2half2_rn(lo, hi);   // identical rounding to old cvt path
    return *reinterpret_cast<uint32_t*>(&h);
}

// ---------------------------------------------------------------------------
// Kernel 1: convert rt s-chunk-0 rows to fp16 (lt is now converted in-match).
// ---------------------------------------------------------------------------
constexpr int NRT0 = BB * TN * DD / 16;   // 32768 16-float units

__global__ void cvt_kernel(const float* __restrict__ rt) {
    int j = blockIdx.x * blockDim.x + threadIdx.x;
    int per_b = TN * DD / 16;              // 1024 units per b
    int b = j / per_b, r = j % per_b;      // rows 0..31 contiguous per b
    const float4* src =
        reinterpret_cast<const float4*>(rt + (size_t)b * TT * DD) + (size_t)r * 4;
    __half* dst = g_rt0 + ((size_t)b * TN * DD + (size_t)r * 16);
    float4 a[4];
#pragma unroll
    for (int k = 0; k < 4; k++) a[k] = src[k];
    uint32_t w[8];
#pragma unroll
    for (int k = 0; k < 4; k++) {
        w[k * 2]     = f2h2(a[k].x, a[k].y);
        w[k * 2 + 1] = f2h2(a[k].z, a[k].w);
    }
    uint4* d = reinterpret_cast<uint4*>(dst);
    d[0] = make_uint4(w[0], w[1], w[2], w[3]);
    d[1] = make_uint4(w[4], w[5], w[6], w[7]);
}

// ---------------------------------------------------------------------------
// Kernel 2: one CTA = (b, t-tile 64, 5 m-planes), 128 threads, 4 CTAs/SM.
// A staged as raw f32 (cp.async direct from input lt) and converted to f16
// per-fragment in registers (identical __floats2half2_rn rounding); B f16
// from pre-converted g_rt0. s-chunk 0 pipelined (ring 2), monotone-safe
// early exit with exact fallback over chunks 1..7 (B from f32 rt in-kernel).
// ---------------------------------------------------------------------------
__global__ __launch_bounds__(NTHR, 4)
void match_kernel(const float* __restrict__ kw, const float* __restrict__ ltf,
                  const float* __restrict__ rtf, float* __restrict__ out) {
    extern __shared__ __align__(128) char smem[];
    const int tid = threadIdx.x;
    const int b   = blockIdx.z;
    const int m0  = blockIdx.y * NM;
    const int t0  = blockIdx.x * TM;
    const uint32_t sbase   = s2u(smem);
    const uint32_t sbuf    = sbase + S_BUF;
    const uint32_t mbfull  = sbase + S_MBAR;        // 2 x 8B
    const uint32_t mbempty = sbase + S_MBAR + 16;   // 2 x 8B

    if (tid == 0) {
#pragma unroll
        for (int i = 0; i < STAGES; i++) {
            asm volatile("mbarrier.init.shared.b64 [%0], %1;"
                         :: "r"(mbfull + 8 * i), "r"((uint32_t)NTHR) : "memory");
            asm volatile("mbarrier.init.shared.b64 [%0], %1;"
                         :: "r"(mbempty + 8 * i), "r"(4u) : "memory");
        }
    }

    // stage km rows (m0..m0+4) as fp16
    __half* kms = reinterpret_cast<__half*>(smem + S_KMS);
#pragma unroll
    for (int e = tid; e < NM * DD; e += NTHR) {
        int mi = e >> 9, c = e & (DD - 1);
        kms[e] = __float2half_rn(kw[(m0 + mi) * DD + c]);
    }
    __syncthreads();   // mbarrier init + kms visible

    const float*  ltb  = ltf   + (size_t)(b * TT + t0) * DD;
    const __half* rt0b = g_rt0 + (size_t)b * TN * DD;
    const float*  rtfb = rtf   + (size_t)b * TT * DD;

    const int wid  = tid >> 5;    // warp = 16 t-rows (4 warps x 16 = 64)
    const int lane = tid & 31;
    const int wt   = wid;         // 0..3
    const int g    = lane >> 2;   // 0..7
    const int q    = lane & 3;    // 0..3

    // A fragment f32 addresses (within stage buffer): rows wt*16+g / +8,
    // cols 2q / 8+2q (per k16 slice kk, add kk*64 bytes)
    const uint32_t a00 = (uint32_t)(wt * 16 + g) * ROWA + (uint32_t)(2 * q) * 4;
    const uint32_t boff = (uint32_t)((lane & 7) + ((lane >> 4) << 3)) * ROWB
                        + ((lane >> 3) & 1) * 16;
    const int c0 = q * 2;

    float runmax[NM][2];
#pragma unroll
    for (int mi = 0; mi < NM; mi++) { runmax[mi][0] = -3.4e38f; runmax[mi][1] = -3.4e38f; }

    int fullp[STAGES]  = {0, 0};
    int emptyp[STAGES] = {1, 1};

    auto issueA = [&](uint32_t sb, int st) {   // A: 64 rows x 16 x 16B f32 chunks
        const int k0 = st * KC;
#pragma unroll
        for (int i = 0; i < 8; i++) {
            int c = tid + i * NTHR, row = c >> 4, sub = c & 15;
            CP16(sb + row * ROWA + sub * 16, ltb + row * DD + k0 + sub * 4);
        }
    };

    auto produce = [&](int st) {        // chunk-0 producer (B from g_rt0)
        const int bfi = st & 1;
        const uint32_t sb = sbuf + bfi * STG_BYTES;
        MBWAIT(mbempty + 8 * bfi, emptyp[bfi]);
        emptyp[bfi] ^= 1;
        issueA(sb, st);
#pragma unroll
        for (int i = 0; i < 2; i++) {   // B: 32 rows x 8 x 16B f16 chunks
            int c = tid + i * NTHR, row = c >> 3, sub = c & 7;
            CP16(sb + A_BYTES + row * ROWB + sub * 16,
                 rt0b + row * DD + st * KC + sub * 8);
        }
        asm volatile("cp.async.mbarrier.arrive.noinc.shared.b64 [%0];"
                     :: "r"(mbfull + 8 * bfi) : "memory");
    };

    // A fragment: 4 float2 LDS + cvt (bit-identical to pre-converted path)
    auto ldfragA = [&](const char* sp, int kk, uint32_t* af) {
        const char* p0 = sp + a00 + kk * 64;
        float2 f0 = *reinterpret_cast<const float2*>(p0);
        float2 f1 = *reinterpret_cast<const float2*>(p0 + 8 * ROWA);
        float2 f2 = *reinterpret_cast<const float2*>(p0 + 32);
        float2 f3 = *reinterpret_cast<const float2*>(p0 + 8 * ROWA + 32);
        af[0] = f2h2(f0.x, f0.y);
        af[1] = f2h2(f1.x, f1.y);
        af[2] = f2h2(f2.x, f2.y);
        af[3] = f2h2(f3.x, f3.y);
    };
    auto ldfragB = [&](uint32_t sb, int kk, uint32_t* bf) {
        LDSM4(bf[0], bf[1], bf[2], bf[3], sb + A_BYTES + boff + kk * 32);
        LDSM4(bf[4], bf[5], bf[6], bf[7], sb + A_BYTES + boff + 16 * ROWB + kk * 32);
    };

    uint32_t acc[NM][4][2];
    auto clear_acc = [&]() {
#pragma unroll
        for (int mi = 0; mi < NM; mi++)
#pragma unroll
            for (int ni = 0; ni < 4; ni++) { acc[mi][ni][0] = 0u; acc[mi][ni][1] = 0u; }
    };

    auto compute = [&](int bfi, int ki) {
        const uint32_t sb = sbuf + bfi * STG_BYTES;
        const char* sp = smem + S_BUF + bfi * STG_BYTES;
        uint32_t bfA[8], afA[4], bfB[8], afB[4];
        ldfragB(sb, 0, bfA);
        ldfragA(sp, 0, afA);
#pragma unroll
        for (int kk = 0; kk < 4; kk++) {
            uint32_t* bf = (kk & 1) ? bfB : bfA;
            uint32_t* af = (kk & 1) ? afB : afA;
            if (kk < 3) {
                ldfragB(sb, kk + 1, (kk & 1) ? bfA : bfB);
                ldfragA(sp, kk + 1, (kk & 1) ? afA : afB);
            }
            const int kb = ki * KC + kk * 16;
#pragma unroll
            for (int mi = 0; mi < NM; mi++) {
                const uint32_t kp0 =
                    *reinterpret_cast<const uint32_t*>(&kms[mi * DD + kb + c0]);
                const uint32_t kp1 =
                    *reinterpret_cast<const uint32_t*>(&kms[mi * DD + kb + c0 + 8]);
                uint32_t a0 = hmul2u(af[0], kp0);
                uint32_t a1 = hmul2u(af[1], kp0);
                uint32_t a2 = hmul2u(af[2], kp1);
                uint32_t a3 = hmul2u(af[3], kp1);
#pragma unroll
                for (int ni = 0; ni < 4; ni++)
                    MMA16816(acc[mi][ni][0], acc[mi][ni][1],
                             a0, a1, a2, a3, bf[ni * 2], bf[ni * 2 + 1]);
            }
        }
    };

    // returns true if every row's running max clears THRESH (monotone-safe)
    auto reduce_vote = [&]() -> int {
        bool pred = true;
#pragma unroll
        for (int mi = 0; mi < NM; mi++)
#pragma unroll
            for (int h = 0; h < 2; h++) {
                __half2 v = *reinterpret_cast<__half2*>(&acc[mi][0][h]);
#pragma unroll
                for (int ni = 1; ni < 4; ni++)
                    v = __hmax2(v, *reinterpret_cast<__half2*>(&acc[mi][ni][h]));
                float fm = fmaxf(__low2float(v), __high2float(v));
                fm = fmaxf(fm, __shfl_xor_sync(0xffffffffu, fm, 1));
                fm = fmaxf(fm, __shfl_xor_sync(0xffffffffu, fm, 2));
                runmax[mi][h] = fmaxf(runmax[mi][h], fm);
                pred = pred && (runmax[mi][h] > THRESH);
            }
        return __syncthreads_and((int)pred);
    };

    // ---- chunk 0: pipelined fast path (ring of 2, produce-ahead 1) ----
    clear_acc();
    produce(0);
#pragma unroll
    for (int ki = 0; ki < NST; ki++) {
        const int bfi = ki & 1;
        MBWAIT(mbfull + 8 * bfi, fullp[bfi]);
        fullp[bfi] ^= 1;
        if (ki + 1 < NST) produce(ki + 1);
        compute(bfi, ki);
        __syncwarp();
        if (lane == 0) {
            asm volatile("{\n\t.reg .b64 t;\n\t"
                         "mbarrier.arrive.shared.b64 t, [%0];\n\t}"
                         :: "r"(mbempty + 8 * bfi) : "memory");
        }
    }
    int done = reduce_vote();

    // ---- chunks 1..7: rare exact fallback (B from f32 rt, converted here) ----
    if (!done) {
        for (int chunk = 1; chunk < NCHK; chunk++) {
            clear_acc();
            for (int ki = 0; ki < NST; ki++) {
                const int bfi = ki & 1;
                const uint32_t sb = sbuf + bfi * STG_BYTES;
                issueA(sb, ki);
                asm volatile("cp.async.commit_group;" ::: "memory");
#pragma unroll
                for (int i = 0; i < 2; i++) {   // B: f32 -> f16 in regs -> STS
                    int c = tid + i * NTHR, row = c >> 3, sub = c & 7;
                    const float* s = rtfb + (size_t)(chunk * TN + row) * DD
                                   + ki * KC + sub * 8;
                    float4 f0 = *reinterpret_cast<const float4*>(s);
                    float4 f1 = *reinterpret_cast<const float4*>(s + 4);
                    uint32_t w0 = f2h2(f0.x, f0.y), w1 = f2h2(f0.z, f0.w);
                    uint32_t w2 = f2h2(f1.x, f1.y), w3 = f2h2(f1.z, f1.w);
                    uint32_t dstp = sb + A_BYTES + row * ROWB + sub * 16;
                    asm volatile("st.shared.v4.b32 [%0], {%1,%2,%3,%4};"
                                 :: "r"(dstp), "r"(w0), "r"(w1), "r"(w2), "r"(w3)
                                 : "memory");
                }
                asm volatile("cp.async.wait_all;" ::: "memory");
                __syncthreads();
                compute(bfi, ki);
                __syncthreads();
            }
            done = reduce_vote();
            if (done) break;
        }
    }

    // write: each 4-lane group holds maxes for rows wt*16 + h*8 + g
    if (q == 0) {
#pragma unroll
        for (int mi = 0; mi < NM; mi++)
#pragma unroll
            for (int h = 0; h < 2; h++) {
                int row = wt * 16 + h * 8 + g;
                out[(size_t)(b * TT + t0 + row) * MPP + (m0 + mi)] =
                    tanhf(runmax[mi][h]);
            }
    }
}

// ---------------------------------------------------------------------------
// Launch: inputs: reps_lt[B,T,D] f32, reps_rt[B,T,D] f32, kernel[1,1,1,MP,D] f32.
// Output [B,T,MP] f32.
// ---------------------------------------------------------------------------
extern "C" void kernel_launch(void* const* d_in, const int* in_sizes, int n_in,
                              void* d_out, int out_size) {
    const float* lt = (const float*)d_in[0];
    const float* rt = (const float*)d_in[1];
    const float* kw = (const float*)d_in[2];
    float* out = (float*)d_out;

    cvt_kernel<<<NRT0 / 256, 256>>>(rt);

    cudaFuncSetAttribute(match_kernel,
                         cudaFuncAttributeMaxDynamicSharedMemorySize, S_TOTAL);
    dim3 grid(TT / TM, MPP / NM, BB);  // (4, 4, 32) = 512 CTAs
    match_kernel<<<grid, NTHR, S_TOTAL>>>(kw, lt, rt, out);
}